// round 6
// baseline (speedup 1.0000x reference)
#include <cuda_runtime.h>
#include <cuda_bf16.h>
#include <cstdint>

// Problem constants
#define BATCH 2
#define SEQ   2048
#define DMODEL 1024
#define NHEAD 16
#define DHEAD 64

__device__ __forceinline__ float to_tf32(float a) {
    float r;
    asm("cvt.rna.tf32.f32 %0, %1;" : "=f"(r) : "f"(a));
    return r;
}

// m16n8k8 tf32 mma, canonical fragment order:
// a0=A[g][t] a1=A[g+8][t] a2=A[g][t+4] a3=A[g+8][t+4]   (g=lane>>2, t=lane&3)
// b0=B[k=t][n=g] b1=B[k=t+4][n=g]
// c0=(g,2t) c1=(g,2t+1) c2=(g+8,2t) c3=(g+8,2t+1)
__device__ __forceinline__ void mma8(float* c, const uint32_t* a,
                                     uint32_t b0, uint32_t b1) {
    asm volatile(
        "mma.sync.aligned.m16n8k8.row.col.f32.tf32.tf32.f32 "
        "{%0,%1,%2,%3}, {%4,%5,%6,%7}, {%8,%9}, {%0,%1,%2,%3};"
        : "+f"(c[0]), "+f"(c[1]), "+f"(c[2]), "+f"(c[3])
        : "r"(a[0]), "r"(a[1]), "r"(a[2]), "r"(a[3]), "r"(b0), "r"(b1));
}

// packed-cell variant used by the (validated) R5 GEMM kernel
__device__ __forceinline__ void mma_tf32(float* c, uint4 a, uint32_t b0_, uint32_t b1_) {
    asm volatile(
        "mma.sync.aligned.m16n8k8.row.col.f32.tf32.tf32.f32 "
        "{%0,%1,%2,%3}, {%4,%5,%6,%7}, {%8,%9}, {%0,%1,%2,%3};"
        : "+f"(c[0]), "+f"(c[1]), "+f"(c[2]), "+f"(c[3])
        : "r"(a.x), "r"(a.z), "r"(a.y), "r"(a.w), "r"(b0_), "r"(b1_));
}

// ===========================================================================
// Scratch
// ===========================================================================
__device__ float g_q[BATCH * NHEAD * SEQ * DHEAD];
__device__ float g_k[BATCH * NHEAD * SEQ * DHEAD];
__device__ float g_v[BATCH * NHEAD * SEQ * DHEAD];
__device__ float g_xt[BATCH * SEQ * DMODEL];
__device__ float g_wt[3 * DMODEL * DMODEL];

// ===========================================================================
// Prep kernels (unchanged from R5)
// ===========================================================================
__global__ __launch_bounds__(256) void prep_x_kernel(const float* __restrict__ x)
{
    int i = blockIdx.x * 256 + threadIdx.x;
    const float4* x4 = (const float4*)x;
    float4 v = x4[i];
    v.x = to_tf32(v.x); v.y = to_tf32(v.y);
    v.z = to_tf32(v.z); v.w = to_tf32(v.w);
    ((float4*)g_xt)[i] = v;
}

__global__ __launch_bounds__(256) void prep_w_kernel(
    const float* __restrict__ W0, const float* __restrict__ W1,
    const float* __restrict__ W2)
{
    __shared__ float t[32][33];
    const int z = blockIdx.z;
    const float* W = (z == 0) ? W0 : (z == 1) ? W1 : W2;
    float* WT = g_wt + (size_t)z * DMODEL * DMODEL;
    const int n0 = blockIdx.x * 32;
    const int k0 = blockIdx.y * 32;
    const int tx = threadIdx.x & 31;
    const int ty = threadIdx.x >> 5;
    #pragma unroll
    for (int r = 0; r < 4; r++)
        t[ty + 8 * r][tx] = to_tf32(W[(size_t)(k0 + ty + 8 * r) * DMODEL + n0 + tx]);
    __syncthreads();
    #pragma unroll
    for (int r = 0; r < 4; r++)
        WT[(size_t)(n0 + ty + 8 * r) * DMODEL + k0 + tx] = t[tx][ty + 8 * r];
}

// ===========================================================================
// QKV GEMM via mma.sync tf32 (R5 winner, unchanged)
// ===========================================================================
#define TKT 32
#define NKT (DMODEL / TKT)
#define STAGEF 8192

__global__ __launch_bounds__(256) void qkv_gemm_mma_kernel(
    const float* __restrict__ b0v, const float* __restrict__ b1v,
    const float* __restrict__ b2v)
{
    extern __shared__ float smf[];

    const int z  = blockIdx.z;
    const int m0 = blockIdx.y * 128;
    const int n0 = blockIdx.x * 128;
    const float* bias = (z == 0) ? b0v : (z == 1) ? b1v : b2v;
    float* outp       = (z == 0) ? g_q : (z == 1) ? g_k : g_v;
    const float* WT   = g_wt + (size_t)z * DMODEL * DMODEL;
    const float* Xp   = g_xt;

    const int tid = threadIdx.x;
    const int wid = tid >> 5;
    const int lid = tid & 31;
    const int warp_m = wid >> 1;
    const int warp_n = wid & 1;
    const int g = lid >> 2;
    const int t = lid & 3;

    float acc[2][8][4];
    #pragma unroll
    for (int a = 0; a < 2; a++)
        #pragma unroll
        for (int n = 0; n < 8; n++)
            #pragma unroll
            for (int c = 0; c < 4; c++) acc[a][n][c] = 0.f;

    int s_kc[2], s_r[2];
    #pragma unroll
    for (int u = 0; u < 2; u++) {
        int f = tid + u * 256;
        s_kc[u] = f >> 7;
        s_r[u]  = f & 127;
    }
    int s_offA[2], s_offB[2];
    #pragma unroll
    for (int u = 0; u < 2; u++) {
        int r = s_r[u], kc = s_kc[u];
        s_offA[u] = (kc * 8 + (r >> 4)) * 128 + (r & 7) * 16 + ((r >> 3) & 1) * 2;
        s_offB[u] = 4096 + s_offA[u];
    }

    #pragma unroll
    for (int u = 0; u < 2; u++) {
        int r = s_r[u], kc = s_kc[u];
        const float4* pA = (const float4*)&Xp[(size_t)(m0 + r) * DMODEL + kc * 8];
        float4 a0 = pA[0], a1 = pA[1];
        float* dA = smf + s_offA[u];
        *(float2*)&dA[0]  = make_float2(a0.x, a1.x);
        *(float2*)&dA[4]  = make_float2(a0.y, a1.y);
        *(float2*)&dA[8]  = make_float2(a0.z, a1.z);
        *(float2*)&dA[12] = make_float2(a0.w, a1.w);
        const float4* pB = (const float4*)&WT[(size_t)(n0 + r) * DMODEL + kc * 8];
        float4 c0 = pB[0], c1 = pB[1];
        float* dB = smf + s_offB[u];
        *(float2*)&dB[0]  = make_float2(c0.x, c1.x);
        *(float2*)&dB[4]  = make_float2(c0.y, c1.y);
        *(float2*)&dB[8]  = make_float2(c0.z, c1.z);
        *(float2*)&dB[12] = make_float2(c0.w, c1.w);
    }
    __syncthreads();

    for (int ktile = 0; ktile < NKT; ktile++) {
        const int buf = ktile & 1;

        float4 ra[4], rb[4];
        if (ktile + 1 < NKT) {
            const int kt = (ktile + 1) * TKT;
            #pragma unroll
            for (int u = 0; u < 2; u++) {
                int r = s_r[u], kc = s_kc[u];
                const float4* pA = (const float4*)&Xp[(size_t)(m0 + r) * DMODEL + kt + kc * 8];
                ra[2 * u]     = pA[0];
                ra[2 * u + 1] = pA[1];
                const float4* pB = (const float4*)&WT[(size_t)(n0 + r) * DMODEL + kt + kc * 8];
                rb[2 * u]     = pB[0];
                rb[2 * u + 1] = pB[1];
            }
        }

        const float* Ap = smf + buf * STAGEF;
        const float* Bp = Ap + 4096;
        #pragma unroll
        for (int kc = 0; kc < 4; kc++) {
            uint4 af[2];
            af[0] = *(const uint4*)&Ap[kc * 1024 + (warp_m * 2 + 0) * 128 + lid * 4];
            af[1] = *(const uint4*)&Ap[kc * 1024 + (warp_m * 2 + 1) * 128 + lid * 4];
            #pragma unroll
            for (int bp = 0; bp < 4; bp++) {
                uint4 bf = *(const uint4*)&Bp[kc * 1024 + (warp_n * 4 + bp) * 128 + lid * 4];
                #pragma unroll
                for (int amt = 0; amt < 2; amt++) {
                    mma_tf32(acc[amt][2 * bp],     af[amt], bf.x, bf.y);
                    mma_tf32(acc[amt][2 * bp + 1], af[amt], bf.z, bf.w);
                }
            }
        }

        if (ktile + 1 < NKT) {
            float* dst = smf + (buf ^ 1) * STAGEF;
            #pragma unroll
            for (int u = 0; u < 2; u++) {
                float4 a0 = ra[2 * u], a1 = ra[2 * u + 1];
                float* dA = dst + s_offA[u];
                *(float2*)&dA[0]  = make_float2(a0.x, a1.x);
                *(float2*)&dA[4]  = make_float2(a0.y, a1.y);
                *(float2*)&dA[8]  = make_float2(a0.z, a1.z);
                *(float2*)&dA[12] = make_float2(a0.w, a1.w);
                float4 c0 = rb[2 * u], c1 = rb[2 * u + 1];
                float* dB = dst + s_offB[u];
                *(float2*)&dB[0]  = make_float2(c0.x, c1.x);
                *(float2*)&dB[4]  = make_float2(c0.y, c1.y);
                *(float2*)&dB[8]  = make_float2(c0.z, c1.z);
                *(float2*)&dB[12] = make_float2(c0.w, c1.w);
            }
        }
        __syncthreads();
    }

    #pragma unroll
    for (int amt = 0; amt < 2; amt++) {
        const int mA = m0 + warp_m * 32 + amt * 16 + g;
        const int bA = mA >> 11;
        const int sA = mA & (SEQ - 1);
        const int mB = mA + 8;
        const int sB = mB & (SEQ - 1);
        #pragma unroll
        for (int nt = 0; nt < 8; nt++) {
            const int n = n0 + warp_n * 64 + nt * 8 + t * 2;
            const int h = n >> 6;
            const int d = n & 63;
            const float2 bb = *(const float2*)&bias[n];
            float* p0 = &outp[(((size_t)(bA * NHEAD + h)) * SEQ + sA) * DHEAD + d];
            float* p1 = &outp[(((size_t)(bA * NHEAD + h)) * SEQ + sB) * DHEAD + d];
            *(float2*)p0 = make_float2(acc[amt][nt][0] + bb.x, acc[amt][nt][1] + bb.y);
            *(float2*)p1 = make_float2(acc[amt][nt][2] + bb.x, acc[amt][nt][3] + bb.y);
        }
    }
}

// ===========================================================================
// Relative-position causal flash attention on mma.sync tf32.
// Per CTA: 128 q-rows, 8 warps (warp w owns rows 16w..16w+15). Per k-tile:
//   QK  : S += Q(128x64) @ K^T(64x128)            [MMA]
//   REL : G = Q @ Band^T (128x256) in 4 chunks of 64 cols, chunk buffer
//         overlays k_s; diagonal gather S[i][j] += G[i][j-i+127]  [MMA+LDS]
//   softmax online (2 rows/thread, quad shuffles), P -> SMEM (tf32)
//   PV  : O += P(128x128) @ V(128x64)             [MMA]
// SMEM: q[128*68] | kG[128*68] | v[128*68] | band[256*68] / p[128*132]
// ===========================================================================
#define AP 68
#define PP 132

__global__ __launch_bounds__(256, 1) void relattn_mma_kernel(
    const float* __restrict__ Er, float* __restrict__ out)
{
    extern __shared__ float sm[];
    float* q_s  = sm;                    // 8704 floats
    float* kg_s = sm + 8704;             // k tile / G chunk buffer
    float* v_s  = sm + 17408;
    float* ep   = sm + 26112;            // band 256x68 / p 128x132

    const int sb = (int)gridDim.x - 1 - (int)blockIdx.x;  // heavy first
    const int bh = blockIdx.y;
    const int b  = bh >> 4;
    const int h  = bh & 15;
    const int s0 = sb * 128;

    const float* Q = g_q + (size_t)bh * SEQ * DHEAD;
    const float* K = g_k + (size_t)bh * SEQ * DHEAD;
    const float* V = g_v + (size_t)bh * SEQ * DHEAD;

    const int tid = threadIdx.x;
    const int wid = tid >> 5;
    const int lid = tid & 31;
    const int g = lid >> 2;
    const int t = lid & 3;
    const int mrow = wid * 16;
    const int i0 = mrow + g;         // CTA-local row of c0/c1
    const int i1 = mrow + g + 8;     // CTA-local row of c2/c3

    // ---- stage q (tf32-rounded) ----
    {
        const float4* Q4 = (const float4*)(Q + (size_t)s0 * DHEAD);
        #pragma unroll
        for (int u = 0; u < 8; u++) {
            int f = tid + u * 256;
            int row = f >> 4, c4 = f & 15;
            float4 v = Q4[row * 16 + c4];
            v.x = to_tf32(v.x); v.y = to_tf32(v.y);
            v.z = to_tf32(v.z); v.w = to_tf32(v.w);
            *(float4*)&q_s[row * AP + c4 * 4] = v;
        }
    }
    __syncthreads();

    // ---- persistent q fragments ----
    uint32_t qf[8][4];
    {
        const uint32_t* qu = (const uint32_t*)q_s;
        #pragma unroll
        for (int kk = 0; kk < 8; kk++) {
            qf[kk][0] = qu[i0 * AP + 8 * kk + t];
            qf[kk][1] = qu[i1 * AP + 8 * kk + t];
            qf[kk][2] = qu[i0 * AP + 8 * kk + t + 4];
            qf[kk][3] = qu[i1 * AP + 8 * kk + t + 4];
        }
    }

    float m_[2] = {-1e30f, -1e30f};
    float l_[2] = {0.f, 0.f};
    float acc_o[8][4];
    #pragma unroll
    for (int n8 = 0; n8 < 8; n8++)
        #pragma unroll
        for (int c = 0; c < 4; c++) acc_o[n8][c] = 0.f;

    const float4* Er4 = (const float4*)Er;
    const uint32_t* kgu = (const uint32_t*)kg_s;
    const uint32_t* epu = (const uint32_t*)ep;
    const uint32_t* vu  = (const uint32_t*)v_s;

    for (int t0 = 0; t0 <= s0; t0 += 128) {
        const bool diag = (t0 == s0);
        __syncthreads();   // prior tile's p/v/G reads done

        // ---- stage k, v, band (tf32-rounded) ----
        {
            const float4* K4 = (const float4*)(K + (size_t)t0 * DHEAD);
            const float4* V4 = (const float4*)(V + (size_t)t0 * DHEAD);
            #pragma unroll
            for (int u = 0; u < 8; u++) {
                int f = tid + u * 256;
                int row = f >> 4, c4 = f & 15;
                float4 kv = K4[row * 16 + c4];
                kv.x = to_tf32(kv.x); kv.y = to_tf32(kv.y);
                kv.z = to_tf32(kv.z); kv.w = to_tf32(kv.w);
                *(float4*)&kg_s[row * AP + c4 * 4] = kv;
                float4 vv = V4[row * 16 + c4];
                vv.x = to_tf32(vv.x); vv.y = to_tf32(vv.y);
                vv.z = to_tf32(vv.z); vv.w = to_tf32(vv.w);
                *(float4*)&v_s[row * AP + c4 * 4] = vv;
            }
            int l0 = t0 - s0 + (SEQ - 1) - 127;
            #pragma unroll
            for (int u = 0; u < 16; u++) {
                int f = tid + u * 256;
                int r = f >> 4, c4 = f & 15;
                int gl = l0 + r;
                gl = gl > SEQ - 1 ? SEQ - 1 : gl;
                float4 ev = Er4[gl * 16 + c4];
                ev.x = to_tf32(ev.x); ev.y = to_tf32(ev.y);
                ev.z = to_tf32(ev.z); ev.w = to_tf32(ev.w);
                *(float4*)&ep[r * AP + c4 * 4] = ev;
            }
        }
        __syncthreads();

        // ---- QK ----
        float acc_s[16][4];
        #pragma unroll
        for (int n8 = 0; n8 < 16; n8++)
            #pragma unroll
            for (int c = 0; c < 4; c++) acc_s[n8][c] = 0.f;

        const int n8max = diag ? (2 * wid + 2) : 16;   // skip fully-masked cols
        #pragma unroll
        for (int kk = 0; kk < 8; kk++) {
            for (int n8 = 0; n8 < n8max; n8++) {
                uint32_t b0 = kgu[(8 * n8 + g) * AP + 8 * kk + t];
                uint32_t b1 = kgu[(8 * n8 + g) * AP + 8 * kk + t + 4];
                mma8(acc_s[n8], qf[kk], b0, b1);
            }
        }
        __syncthreads();   // all QK reads of kg_s done before G overwrites it

        // ---- REL: G chunks + diagonal gather ----
        const int cmax = diag ? 2 : 4;   // chunks >=2 feed only masked cells
        for (int c = 0; c < cmax; c++) {
            float acc_g[8][4];
            #pragma unroll
            for (int n8 = 0; n8 < 8; n8++)
                #pragma unroll
                for (int cc = 0; cc < 4; cc++) acc_g[n8][cc] = 0.f;

            #pragma unroll
            for (int kk = 0; kk < 8; kk++)
                #pragma unroll
                for (int n8 = 0; n8 < 8; n8++) {
                    uint32_t b0 = epu[(64 * c + 8 * n8 + g) * AP + 8 * kk + t];
                    uint32_t b1 = epu[(64 * c + 8 * n8 + g) * AP + 8 * kk + t + 4];
                    mma8(acc_g[n8], qf[kk], b0, b1);
                }

            #pragma unroll
            for (int n8 = 0; n8 < 8; n8++) {
                *(float2*)&kg_s[i0 * AP + 8 * n8 + 2 * t] =
                    make_float2(acc_g[n8][0], acc_g[n8][1]);
                *(float2*)&kg_s[i1 * AP + 8 * n8 + 2 * t] =
                    make_float2(acc_g[n8][2], acc_g[n8][3]);
            }
            __syncthreads();

            // gather: S[i][j] += G[i][j-i+127], chunk covers l' in [64c,64c+64)
            #pragma unroll
            for (int n8 = 0; n8 < 16; n8++) {
                int j = 8 * n8 + 2 * t;
                int lp0 = j - i0 + 127 - 64 * c;
                if (lp0 >= 0 && lp0 < 64)      acc_s[n8][0] += kg_s[i0 * AP + lp0];
                if (lp0 + 1 >= 0 && lp0 + 1 < 64) acc_s[n8][1] += kg_s[i0 * AP + lp0 + 1];
                int lp1 = j - i1 + 127 - 64 * c;
                if (lp1 >= 0 && lp1 < 64)      acc_s[n8][2] += kg_s[i1 * AP + lp1];
                if (lp1 + 1 >= 0 && lp1 + 1 < 64) acc_s[n8][3] += kg_s[i1 * AP + lp1 + 1];
            }
            __syncthreads();
        }

        // ---- mask + scale + row max ----
        float mx0 = -1e30f, mx1 = -1e30f;
        #pragma unroll
        for (int n8 = 0; n8 < 16; n8++) {
            int j = 8 * n8 + 2 * t;
            float v0 = acc_s[n8][0] * 0.125f;
            float v1 = acc_s[n8][1] * 0.125f;
            float v2 = acc_s[n8][2] * 0.125f;
            float v3 = acc_s[n8][3] * 0.125f;
            if (diag) {
                if (j     > i0) v0 = -1e30f;
                if (j + 1 > i0) v1 = -1e30f;
                if (j     > i1) v2 = -1e30f;
                if (j + 1 > i1) v3 = -1e30f;
            }
            acc_s[n8][0] = v0; acc_s[n8][1] = v1;
            acc_s[n8][2] = v2; acc_s[n8][3] = v3;
            mx0 = fmaxf(mx0, fmaxf(v0, v1));
            mx1 = fmaxf(mx1, fmaxf(v2, v3));
        }
        mx0 = fmaxf(mx0, __shfl_xor_sync(0xffffffffu, mx0, 1));
        mx0 = fmaxf(mx0, __shfl_xor_sync(0xffffffffu, mx0, 2));
        mx1 = fmaxf(mx1, __shfl_xor_sync(0xffffffffu, mx1, 1));
        mx1 = fmaxf(mx1, __shfl_xor_sync(0xffffffffu, mx1, 2));

        // ---- online softmax; write P (tf32) ----
        float mn0 = fmaxf(m_[0], mx0);
        float mn1 = fmaxf(m_[1], mx1);
        float al0 = __expf(m_[0] - mn0);
        float al1 = __expf(m_[1] - mn1);
        m_[0] = mn0; m_[1] = mn1;
        float ls0 = 0.f, ls1 = 0.f;
        #pragma unroll
        for (int n8 = 0; n8 < 16; n8++) {
            int j = 8 * n8 + 2 * t;
            float p0 = to_tf32(__expf(acc_s[n8][0] - mn0));
            float p1 = to_tf32(__expf(acc_s[n8][1] - mn0));
            float p2 = to_tf32(__expf(acc_s[n8][2] - mn1));
            float p3 = to_tf32(__expf(acc_s[n8][3] - mn1));
            ls0 += p0 + p1;
            ls1 += p2 + p3;
            *(float2*)&ep[i0 * PP + j] = make_float2(p0, p1);
            *(float2*)&ep[i1 * PP + j] = make_float2(p2, p3);
        }
        ls0 += __shfl_xor_sync(0xffffffffu, ls0, 1);
        ls0 += __shfl_xor_sync(0xffffffffu, ls0, 2);
        ls1 += __shfl_xor_sync(0xffffffffu, ls1, 1);
        ls1 += __shfl_xor_sync(0xffffffffu, ls1, 2);
        l_[0] = l_[0] * al0 + ls0;
        l_[1] = l_[1] * al1 + ls1;
        #pragma unroll
        for (int n8 = 0; n8 < 8; n8++) {
            acc_o[n8][0] *= al0; acc_o[n8][1] *= al0;
            acc_o[n8][2] *= al1; acc_o[n8][3] *= al1;
        }
        __syncthreads();   // P visible to all warps

        // ---- PV ----
        const int kkmax = diag ? (2 * wid + 2) : 16;  // skip all-zero P blocks
        for (int kk = 0; kk < kkmax; kk++) {
            uint32_t pf[4];
            pf[0] = epu[i0 * PP + 8 * kk + t];
            pf[1] = epu[i1 * PP + 8 * kk + t];
            pf[2] = epu[i0 * PP + 8 * kk + t + 4];
            pf[3] = epu[i1 * PP + 8 * kk + t + 4];
            #pragma unroll
            for (int n8 = 0; n8 < 8; n8++) {
                uint32_t b0 = vu[(8 * kk + t) * AP + 8 * n8 + g];
                uint32_t b1 = vu[(8 * kk + t + 4) * AP + 8 * n8 + g];
                mma8(acc_o[n8], pf, b0, b1);
            }
        }
    }

    // ---- epilogue ----
    float inv0 = 1.f / l_[0];
    float inv1 = 1.f / l_[1];
    #pragma unroll
    for (int n8 = 0; n8 < 8; n8++) {
        int d = 8 * n8 + 2 * t;
        int sg0 = s0 + i0;
        int sg1 = s0 + i1;
        *(float2*)&out[((size_t)b * SEQ + sg0) * DMODEL + h * DHEAD + d] =
            make_float2(acc_o[n8][0] * inv0, acc_o[n8][1] * inv0);
        *(float2*)&out[((size_t)b * SEQ + sg1) * DMODEL + h * DHEAD + d] =
            make_float2(acc_o[n8][2] * inv1, acc_o[n8][3] * inv1);
    }
}

// ===========================================================================
extern "C" void kernel_launch(void* const* d_in, const int* in_sizes, int n_in,
                              void* d_out, int out_size)
{
    const float* x  = (const float*)d_in[0];
    const float* Wq = (const float*)d_in[1];
    const float* bq = (const float*)d_in[2];
    const float* Wk = (const float*)d_in[3];
    const float* bk = (const float*)d_in[4];
    const float* Wv = (const float*)d_in[5];
    const float* bv = (const float*)d_in[6];
    const float* Er = (const float*)d_in[7];
    float* out = (float*)d_out;

    (void)in_sizes; (void)n_in; (void)out_size;

    const int attn_smem = 43520 * 4;    // 174080
    cudaFuncSetAttribute(relattn_mma_kernel,
                         cudaFuncAttributeMaxDynamicSharedMemorySize, attn_smem);
    const int gemm_smem = 2 * STAGEF * 4;
    cudaFuncSetAttribute(qkv_gemm_mma_kernel,
                         cudaFuncAttributeMaxDynamicSharedMemorySize, gemm_smem);

    prep_x_kernel<<<(BATCH * SEQ * DMODEL) / (4 * 256), 256>>>(x);
    prep_w_kernel<<<dim3(DMODEL / 32, DMODEL / 32, 3), 256>>>(Wq, Wk, Wv);

    dim3 gg(DMODEL / 128, (BATCH * SEQ) / 128, 3);
    qkv_gemm_mma_kernel<<<gg, 256, gemm_smem>>>(bq, bk, bv);

    dim3 g2(SEQ / 128, BATCH * NHEAD);
    relattn_mma_kernel<<<g2, 256, attn_smem>>>(Er, out);
}

// round 7
// speedup vs baseline: 1.9428x; 1.9428x over previous
#include <cuda_runtime.h>
#include <cuda_bf16.h>
#include <cstdint>

// Problem constants
#define BATCH 2
#define SEQ   2048
#define DMODEL 1024
#define NHEAD 16
#define DHEAD 64

__device__ __forceinline__ float to_tf32(float a) {
    float r;
    asm("cvt.rna.tf32.f32 %0, %1;" : "=f"(r) : "f"(a));
    return r;
}
__device__ __forceinline__ float4 round4(float4 v) {
    v.x = to_tf32(v.x); v.y = to_tf32(v.y);
    v.z = to_tf32(v.z); v.w = to_tf32(v.w);
    return v;
}

// m16n8k8 tf32 mma, canonical fragment order (g=lane>>2, t=lane&3):
// a0=A[g][t] a1=A[g+8][t] a2=A[g][t+4] a3=A[g+8][t+4]
// b0=B[k=t][n=g] b1=B[k=t+4][n=g]
// c0=(g,2t) c1=(g,2t+1) c2=(g+8,2t) c3=(g+8,2t+1)
__device__ __forceinline__ void mma8(float* c, const uint32_t* a,
                                     uint32_t b0, uint32_t b1) {
    asm volatile(
        "mma.sync.aligned.m16n8k8.row.col.f32.tf32.tf32.f32 "
        "{%0,%1,%2,%3}, {%4,%5,%6,%7}, {%8,%9}, {%0,%1,%2,%3};"
        : "+f"(c[0]), "+f"(c[1]), "+f"(c[2]), "+f"(c[3])
        : "r"(a[0]), "r"(a[1]), "r"(a[2]), "r"(a[3]), "r"(b0), "r"(b1));
}
__device__ __forceinline__ void mma_tf32(float* c, uint4 a, uint32_t b0_, uint32_t b1_) {
    asm volatile(
        "mma.sync.aligned.m16n8k8.row.col.f32.tf32.tf32.f32 "
        "{%0,%1,%2,%3}, {%4,%5,%6,%7}, {%8,%9}, {%0,%1,%2,%3};"
        : "+f"(c[0]), "+f"(c[1]), "+f"(c[2]), "+f"(c[3])
        : "r"(a.x), "r"(a.z), "r"(a.y), "r"(a.w), "r"(b0_), "r"(b1_));
}

// ===========================================================================
// Scratch
// ===========================================================================
__device__ float g_q[BATCH * NHEAD * SEQ * DHEAD];
__device__ float g_k[BATCH * NHEAD * SEQ * DHEAD];
__device__ float g_v[BATCH * NHEAD * SEQ * DHEAD];
__device__ float g_xt[BATCH * SEQ * DMODEL];
__device__ float g_wt[3 * DMODEL * DMODEL];

// ===========================================================================
// Prep kernels (R5, unchanged)
// ===========================================================================
__global__ __launch_bounds__(256) void prep_x_kernel(const float* __restrict__ x)
{
    int i = blockIdx.x * 256 + threadIdx.x;
    const float4* x4 = (const float4*)x;
    ((float4*)g_xt)[i] = round4(x4[i]);
}

__global__ __launch_bounds__(256) void prep_w_kernel(
    const float* __restrict__ W0, const float* __restrict__ W1,
    const float* __restrict__ W2)
{
    __shared__ float t[32][33];
    const int z = blockIdx.z;
    const float* W = (z == 0) ? W0 : (z == 1) ? W1 : W2;
    float* WT = g_wt + (size_t)z * DMODEL * DMODEL;
    const int n0 = blockIdx.x * 32;
    const int k0 = blockIdx.y * 32;
    const int tx = threadIdx.x & 31;
    const int ty = threadIdx.x >> 5;
    #pragma unroll
    for (int r = 0; r < 4; r++)
        t[ty + 8 * r][tx] = to_tf32(W[(size_t)(k0 + ty + 8 * r) * DMODEL + n0 + tx]);
    __syncthreads();
    #pragma unroll
    for (int r = 0; r < 4; r++)
        WT[(size_t)(n0 + ty + 8 * r) * DMODEL + k0 + tx] = t[tx][ty + 8 * r];
}

// ===========================================================================
// QKV GEMM via mma.sync tf32 (R5 winner, unchanged)
// ===========================================================================
#define TKT 32
#define NKT (DMODEL / TKT)
#define STAGEF 8192

__global__ __launch_bounds__(256) void qkv_gemm_mma_kernel(
    const float* __restrict__ b0v, const float* __restrict__ b1v,
    const float* __restrict__ b2v)
{
    extern __shared__ float smf[];

    const int z  = blockIdx.z;
    const int m0 = blockIdx.y * 128;
    const int n0 = blockIdx.x * 128;
    const float* bias = (z == 0) ? b0v : (z == 1) ? b1v : b2v;
    float* outp       = (z == 0) ? g_q : (z == 1) ? g_k : g_v;
    const float* WT   = g_wt + (size_t)z * DMODEL * DMODEL;
    const float* Xp   = g_xt;

    const int tid = threadIdx.x;
    const int wid = tid >> 5;
    const int lid = tid & 31;
    const int warp_m = wid >> 1;
    const int warp_n = wid & 1;
    const int g = lid >> 2;
    const int t = lid & 3;

    float acc[2][8][4];
    #pragma unroll
    for (int a = 0; a < 2; a++)
        #pragma unroll
        for (int n = 0; n < 8; n++)
            #pragma unroll
            for (int c = 0; c < 4; c++) acc[a][n][c] = 0.f;

    int s_kc[2], s_r[2];
    #pragma unroll
    for (int u = 0; u < 2; u++) {
        int f = tid + u * 256;
        s_kc[u] = f >> 7;
        s_r[u]  = f & 127;
    }
    int s_offA[2], s_offB[2];
    #pragma unroll
    for (int u = 0; u < 2; u++) {
        int r = s_r[u], kc = s_kc[u];
        s_offA[u] = (kc * 8 + (r >> 4)) * 128 + (r & 7) * 16 + ((r >> 3) & 1) * 2;
        s_offB[u] = 4096 + s_offA[u];
    }

    #pragma unroll
    for (int u = 0; u < 2; u++) {
        int r = s_r[u], kc = s_kc[u];
        const float4* pA = (const float4*)&Xp[(size_t)(m0 + r) * DMODEL + kc * 8];
        float4 a0 = pA[0], a1 = pA[1];
        float* dA = smf + s_offA[u];
        *(float2*)&dA[0]  = make_float2(a0.x, a1.x);
        *(float2*)&dA[4]  = make_float2(a0.y, a1.y);
        *(float2*)&dA[8]  = make_float2(a0.z, a1.z);
        *(float2*)&dA[12] = make_float2(a0.w, a1.w);
        const float4* pB = (const float4*)&WT[(size_t)(n0 + r) * DMODEL + kc * 8];
        float4 c0 = pB[0], c1 = pB[1];
        float* dB = smf + s_offB[u];
        *(float2*)&dB[0]  = make_float2(c0.x, c1.x);
        *(float2*)&dB[4]  = make_float2(c0.y, c1.y);
        *(float2*)&dB[8]  = make_float2(c0.z, c1.z);
        *(float2*)&dB[12] = make_float2(c0.w, c1.w);
    }
    __syncthreads();

    for (int ktile = 0; ktile < NKT; ktile++) {
        const int buf = ktile & 1;

        float4 ra[4], rb[4];
        if (ktile + 1 < NKT) {
            const int kt = (ktile + 1) * TKT;
            #pragma unroll
            for (int u = 0; u < 2; u++) {
                int r = s_r[u], kc = s_kc[u];
                const float4* pA = (const float4*)&Xp[(size_t)(m0 + r) * DMODEL + kt + kc * 8];
                ra[2 * u]     = pA[0];
                ra[2 * u + 1] = pA[1];
                const float4* pB = (const float4*)&WT[(size_t)(n0 + r) * DMODEL + kt + kc * 8];
                rb[2 * u]     = pB[0];
                rb[2 * u + 1] = pB[1];
            }
        }

        const float* Ap = smf + buf * STAGEF;
        const float* Bp = Ap + 4096;
        #pragma unroll
        for (int kc = 0; kc < 4; kc++) {
            uint4 af[2];
            af[0] = *(const uint4*)&Ap[kc * 1024 + (warp_m * 2 + 0) * 128 + lid * 4];
            af[1] = *(const uint4*)&Ap[kc * 1024 + (warp_m * 2 + 1) * 128 + lid * 4];
            #pragma unroll
            for (int bp = 0; bp < 4; bp++) {
                uint4 bf = *(const uint4*)&Bp[kc * 1024 + (warp_n * 4 + bp) * 128 + lid * 4];
                #pragma unroll
                for (int amt = 0; amt < 2; amt++) {
                    mma_tf32(acc[amt][2 * bp],     af[amt], bf.x, bf.y);
                    mma_tf32(acc[amt][2 * bp + 1], af[amt], bf.z, bf.w);
                }
            }
        }

        if (ktile + 1 < NKT) {
            float* dst = smf + (buf ^ 1) * STAGEF;
            #pragma unroll
            for (int u = 0; u < 2; u++) {
                float4 a0 = ra[2 * u], a1 = ra[2 * u + 1];
                float* dA = dst + s_offA[u];
                *(float2*)&dA[0]  = make_float2(a0.x, a1.x);
                *(float2*)&dA[4]  = make_float2(a0.y, a1.y);
                *(float2*)&dA[8]  = make_float2(a0.z, a1.z);
                *(float2*)&dA[12] = make_float2(a0.w, a1.w);
                float4 c0 = rb[2 * u], c1 = rb[2 * u + 1];
                float* dB = dst + s_offB[u];
                *(float2*)&dB[0]  = make_float2(c0.x, c1.x);
                *(float2*)&dB[4]  = make_float2(c0.y, c1.y);
                *(float2*)&dB[8]  = make_float2(c0.z, c1.z);
                *(float2*)&dB[12] = make_float2(c0.w, c1.w);
            }
        }
        __syncthreads();
    }

    #pragma unroll
    for (int amt = 0; amt < 2; amt++) {
        const int mA = m0 + warp_m * 32 + amt * 16 + g;
        const int bA = mA >> 11;
        const int sA = mA & (SEQ - 1);
        const int mB = mA + 8;
        const int sB = mB & (SEQ - 1);
        #pragma unroll
        for (int nt = 0; nt < 8; nt++) {
            const int n = n0 + warp_n * 64 + nt * 8 + t * 2;
            const int h = n >> 6;
            const int d = n & 63;
            const float2 bb = *(const float2*)&bias[n];
            float* p0 = &outp[(((size_t)(bA * NHEAD + h)) * SEQ + sA) * DHEAD + d];
            float* p1 = &outp[(((size_t)(bA * NHEAD + h)) * SEQ + sB) * DHEAD + d];
            *(float2*)p0 = make_float2(acc[amt][nt][0] + bb.x, acc[amt][nt][1] + bb.y);
            *(float2*)p1 = make_float2(acc[amt][nt][2] + bb.x, acc[amt][nt][3] + bb.y);
        }
    }
}

// ===========================================================================
// Relative-position causal flash attention, mma.sync tf32, v2.
// Paired-chunk k-permutation: one float4 LDS feeds two m16n8k8 mmas.
// Chunk 2u k-set positions p: d = 16u+4p (p<4), 16u+4(p-4)+1 (p>=4);
// chunk 2u+1: +2 / +3. Valid because the same permutation is applied to both
// operands.
// SMEM: k[128x80] | vT[64x144, col-XOR-swizzle] | band[256x80]/P[128x144] |
//       G[128x72].  G and P rows are warp-private -> __syncwarp only.
// 2 CTA barriers per k-tile (staging).
// ===========================================================================
#define KP  80
#define VP  144
#define BP  80
#define PPL 144
#define GP  72
#define OFF_K   0
#define OFF_VT  10240              // 128*80
#define OFF_BPD 19456              // + 64*144
#define OFF_G   39936              // + 256*80
#define ATT_FLOATS 49152           // + 128*72
#define ATT_SMEM (ATT_FLOATS * 4)  // 196608

__global__ __launch_bounds__(256, 1) void relattn_mma_kernel(
    const float* __restrict__ Er, float* __restrict__ out)
{
    extern __shared__ float sm[];
    float* k_s  = sm + OFF_K;
    float* vt_s = sm + OFF_VT;
    float* bp_s = sm + OFF_BPD;     // band, then P (band dead after REL)
    float* g_s  = sm + OFF_G;

    const int sb = (int)gridDim.x - 1 - (int)blockIdx.x;  // heavy first
    const int bh = blockIdx.y;
    const int b  = bh >> 4;
    const int h  = bh & 15;
    const int s0 = sb * 128;

    const float* Q = g_q + (size_t)bh * SEQ * DHEAD;
    const float* K = g_k + (size_t)bh * SEQ * DHEAD;
    const float* V = g_v + (size_t)bh * SEQ * DHEAD;

    const int tid = threadIdx.x;
    const int wid = tid >> 5;
    const int lid = tid & 31;
    const int g = lid >> 2;
    const int t = lid & 3;
    const int i0 = wid * 16 + g;
    const int i1 = i0 + 8;

    // ---- persistent q fragments straight from gmem ----
    uint32_t qf[8][4];
    #pragma unroll
    for (int u = 0; u < 4; u++) {
        float4 q0 = round4(*(const float4*)&Q[(size_t)(s0 + i0) * DHEAD + 16 * u + 4 * t]);
        float4 q1 = round4(*(const float4*)&Q[(size_t)(s0 + i1) * DHEAD + 16 * u + 4 * t]);
        qf[2 * u][0] = __float_as_uint(q0.x); qf[2 * u][1] = __float_as_uint(q1.x);
        qf[2 * u][2] = __float_as_uint(q0.y); qf[2 * u][3] = __float_as_uint(q1.y);
        qf[2 * u + 1][0] = __float_as_uint(q0.z); qf[2 * u + 1][1] = __float_as_uint(q1.z);
        qf[2 * u + 1][2] = __float_as_uint(q0.w); qf[2 * u + 1][3] = __float_as_uint(q1.w);
    }

    float m_[2] = {-1e30f, -1e30f};
    float l_[2] = {0.f, 0.f};
    float acc_o[8][4];
    #pragma unroll
    for (int n8 = 0; n8 < 8; n8++)
        #pragma unroll
        for (int c = 0; c < 4; c++) acc_o[n8][c] = 0.f;

    const float4* Er4 = (const float4*)Er;
    const int vxor = 4 * (((8 * 0 + g) >> 2) & 3);  // placeholder (recomputed per n8)
    (void)vxor;

    for (int t0 = 0; t0 <= s0; t0 += 128) {
        const bool diag = (t0 == s0);
        __syncthreads();   // prior tile reads of k/vT/band-P done

        // ---- stage k, vT (swizzled transpose), band (all tf32-rounded) ----
        {
            const float4* K4 = (const float4*)(K + (size_t)t0 * DHEAD);
            const float4* V4 = (const float4*)(V + (size_t)t0 * DHEAD);
            #pragma unroll
            for (int u = 0; u < 8; u++) {
                int f = tid + u * 256;
                int row = f >> 4, c4 = f & 15;
                *(float4*)&k_s[row * KP + c4 * 4] = round4(K4[row * 16 + c4]);
                float4 vv = round4(V4[row * 16 + c4]);
                int sw = row ^ (4 * (c4 & 3));
                vt_s[(4 * c4 + 0) * VP + sw] = vv.x;
                vt_s[(4 * c4 + 1) * VP + sw] = vv.y;
                vt_s[(4 * c4 + 2) * VP + sw] = vv.z;
                vt_s[(4 * c4 + 3) * VP + sw] = vv.w;
            }
            int l0 = t0 - s0 + (SEQ - 1) - 127;
            #pragma unroll
            for (int u = 0; u < 16; u++) {
                int f = tid + u * 256;
                int r = f >> 4, c4 = f & 15;
                int gl = l0 + r;
                gl = gl > SEQ - 1 ? SEQ - 1 : gl;
                *(float4*)&bp_s[r * BP + c4 * 4] = round4(Er4[gl * 16 + c4]);
            }
        }
        __syncthreads();

        // ---- QK ----
        float acc_s[16][4];
        #pragma unroll
        for (int n8 = 0; n8 < 16; n8++)
            #pragma unroll
            for (int c = 0; c < 4; c++) acc_s[n8][c] = 0.f;

        #pragma unroll
        for (int u = 0; u < 4; u++) {
            #pragma unroll
            for (int n8 = 0; n8 < 16; n8++) {
                if (diag && n8 > 2 * wid + 1) continue;
                const uint4 kb = *(const uint4*)&k_s[(8 * n8 + g) * KP + 16 * u + 4 * t];
                mma8(acc_s[n8], qf[2 * u],     kb.x, kb.y);
                mma8(acc_s[n8], qf[2 * u + 1], kb.z, kb.w);
            }
        }

        // ---- REL: G chunks (warp-private rows) + diagonal gather ----
        #pragma unroll
        for (int c = 0; c < 4; c++) {
            if (diag && c >= 2) continue;
            float acc_g[8][4];
            #pragma unroll
            for (int n8 = 0; n8 < 8; n8++)
                #pragma unroll
                for (int cc = 0; cc < 4; cc++) acc_g[n8][cc] = 0.f;

            #pragma unroll
            for (int u = 0; u < 4; u++)
                #pragma unroll
                for (int n8 = 0; n8 < 8; n8++) {
                    const uint4 bb = *(const uint4*)&bp_s[(64 * c + 8 * n8 + g) * BP + 16 * u + 4 * t];
                    mma8(acc_g[n8], qf[2 * u],     bb.x, bb.y);
                    mma8(acc_g[n8], qf[2 * u + 1], bb.z, bb.w);
                }

            __syncwarp();   // prior chunk's gather reads done
            #pragma unroll
            for (int n8 = 0; n8 < 8; n8++) {
                *(float2*)&g_s[i0 * GP + 8 * n8 + 2 * t] = make_float2(acc_g[n8][0], acc_g[n8][1]);
                *(float2*)&g_s[i1 * GP + 8 * n8 + 2 * t] = make_float2(acc_g[n8][2], acc_g[n8][3]);
            }
            __syncwarp();

            #pragma unroll
            for (int n8 = 0; n8 < 16; n8++) {
                if (diag && n8 > 2 * wid + 1) continue;
                int j = 8 * n8 + 2 * t;
                int lp0 = j - i0 + 127 - 64 * c;
                int lp1 = j - i1 + 127 - 64 * c;
                if (lp0 >= 0 && lp0 < 64)         acc_s[n8][0] += g_s[i0 * GP + lp0];
                if (lp0 + 1 >= 0 && lp0 + 1 < 64) acc_s[n8][1] += g_s[i0 * GP + lp0 + 1];
                if (lp1 >= 0 && lp1 < 64)         acc_s[n8][2] += g_s[i1 * GP + lp1];
                if (lp1 + 1 >= 0 && lp1 + 1 < 64) acc_s[n8][3] += g_s[i1 * GP + lp1 + 1];
            }
        }
        __syncwarp();   // gather reads done before next use of g_s

        // ---- mask + scale + row max ----
        float mx0 = -1e30f, mx1 = -1e30f;
        #pragma unroll
        for (int n8 = 0; n8 < 16; n8++) {
            int j = 8 * n8 + 2 * t;
            float v0 = acc_s[n8][0] * 0.125f;
            float v1 = acc_s[n8][1] * 0.125f;
            float v2 = acc_s[n8][2] * 0.125f;
            float v3 = acc_s[n8][3] * 0.125f;
            if (diag) {
                if (j     > i0) v0 = -1e30f;
                if (j + 1 > i0) v1 = -1e30f;
                if (j     > i1) v2 = -1e30f;
                if (j + 1 > i1) v3 = -1e30f;
            }
            acc_s[n8][0] = v0; acc_s[n8][1] = v1;
            acc_s[n8][2] = v2; acc_s[n8][3] = v3;
            mx0 = fmaxf(mx0, fmaxf(v0, v1));
            mx1 = fmaxf(mx1, fmaxf(v2, v3));
        }
        mx0 = fmaxf(mx0, __shfl_xor_sync(0xffffffffu, mx0, 1));
        mx0 = fmaxf(mx0, __shfl_xor_sync(0xffffffffu, mx0, 2));
        mx1 = fmaxf(mx1, __shfl_xor_sync(0xffffffffu, mx1, 1));
        mx1 = fmaxf(mx1, __shfl_xor_sync(0xffffffffu, mx1, 2));

        // ---- online softmax; write P (tf32) to warp-private rows ----
        float mn0 = fmaxf(m_[0], mx0);
        float mn1 = fmaxf(m_[1], mx1);
        float al0 = __expf(m_[0] - mn0);
        float al1 = __expf(m_[1] - mn1);
        m_[0] = mn0; m_[1] = mn1;
        float ls0 = 0.f, ls1 = 0.f;
        #pragma unroll
        for (int n8 = 0; n8 < 16; n8++) {
            int j = 8 * n8 + 2 * t;
            float p0 = to_tf32(__expf(acc_s[n8][0] - mn0));
            float p1 = to_tf32(__expf(acc_s[n8][1] - mn0));
            float p2 = to_tf32(__expf(acc_s[n8][2] - mn1));
            float p3 = to_tf32(__expf(acc_s[n8][3] - mn1));
            ls0 += p0 + p1;
            ls1 += p2 + p3;
            *(float2*)&bp_s[i0 * PPL + j] = make_float2(p0, p1);
            *(float2*)&bp_s[i1 * PPL + j] = make_float2(p2, p3);
        }
        ls0 += __shfl_xor_sync(0xffffffffu, ls0, 1);
        ls0 += __shfl_xor_sync(0xffffffffu, ls0, 2);
        ls1 += __shfl_xor_sync(0xffffffffu, ls1, 1);
        ls1 += __shfl_xor_sync(0xffffffffu, ls1, 2);
        l_[0] = l_[0] * al0 + ls0;
        l_[1] = l_[1] * al1 + ls1;
        #pragma unroll
        for (int n8 = 0; n8 < 8; n8++) {
            acc_o[n8][0] *= al0; acc_o[n8][1] *= al0;
            acc_o[n8][2] *= al1; acc_o[n8][3] *= al1;
        }
        __syncwarp();   // P visible within warp

        // ---- PV: O += P @ V, chunk-paired float4 loads ----
        #pragma unroll
        for (int u = 0; u < 8; u++) {
            if (diag && u > wid) continue;
            const float4 p0 = *(const float4*)&bp_s[i0 * PPL + 16 * u + 4 * t];
            const float4 p1 = *(const float4*)&bp_s[i1 * PPL + 16 * u + 4 * t];
            uint32_t pfA[4] = {__float_as_uint(p0.x), __float_as_uint(p1.x),
                               __float_as_uint(p0.y), __float_as_uint(p1.y)};
            uint32_t pfB[4] = {__float_as_uint(p0.z), __float_as_uint(p1.z),
                               __float_as_uint(p0.w), __float_as_uint(p1.w)};
            #pragma unroll
            for (int n8 = 0; n8 < 8; n8++) {
                int d = 8 * n8 + g;
                int xr = 4 * ((d >> 2) & 3);
                const uint4 vb = *(const uint4*)&vt_s[d * VP + (16 * u + ((4 * t) ^ xr))];
                mma8(acc_o[n8], pfA, vb.x, vb.y);
                mma8(acc_o[n8], pfB, vb.z, vb.w);
            }
        }
        __syncwarp();   // P reads done before next tile overwrites bp_s
    }

    // ---- epilogue ----
    float inv0 = 1.f / l_[0];
    float inv1 = 1.f / l_[1];
    #pragma unroll
    for (int n8 = 0; n8 < 8; n8++) {
        int d = 8 * n8 + 2 * t;
        int sg0 = s0 + i0;
        int sg1 = s0 + i1;
        *(float2*)&out[((size_t)b * SEQ + sg0) * DMODEL + h * DHEAD + d] =
            make_float2(acc_o[n8][0] * inv0, acc_o[n8][1] * inv0);
        *(float2*)&out[((size_t)b * SEQ + sg1) * DMODEL + h * DHEAD + d] =
            make_float2(acc_o[n8][2] * inv1, acc_o[n8][3] * inv1);
    }
}

// ===========================================================================
extern "C" void kernel_launch(void* const* d_in, const int* in_sizes, int n_in,
                              void* d_out, int out_size)
{
    const float* x  = (const float*)d_in[0];
    const float* Wq = (const float*)d_in[1];
    const float* bq = (const float*)d_in[2];
    const float* Wk = (const float*)d_in[3];
    const float* bk = (const float*)d_in[4];
    const float* Wv = (const float*)d_in[5];
    const float* bv = (const float*)d_in[6];
    const float* Er = (const float*)d_in[7];
    float* out = (float*)d_out;

    (void)in_sizes; (void)n_in; (void)out_size;

    cudaFuncSetAttribute(relattn_mma_kernel,
                         cudaFuncAttributeMaxDynamicSharedMemorySize, ATT_SMEM);
    const int gemm_smem = 2 * STAGEF * 4;
    cudaFuncSetAttribute(qkv_gemm_mma_kernel,
                         cudaFuncAttributeMaxDynamicSharedMemorySize, gemm_smem);

    prep_x_kernel<<<(BATCH * SEQ * DMODEL) / (4 * 256), 256>>>(x);
    prep_w_kernel<<<dim3(DMODEL / 32, DMODEL / 32, 3), 256>>>(Wq, Wk, Wv);

    dim3 gg(DMODEL / 128, (BATCH * SEQ) / 128, 3);
    qkv_gemm_mma_kernel<<<gg, 256, gemm_smem>>>(bq, bk, bv);

    dim3 g2(SEQ / 128, BATCH * NHEAD);
    relattn_mma_kernel<<<g2, 256, ATT_SMEM>>>(Er, out);
}